// round 1
// baseline (speedup 1.0000x reference)
#include <cuda_runtime.h>
#include <math.h>

// ---------------- problem constants ----------------
#define Dm     1024
#define Lnum   2
#define Hh     16
#define DHh    64
#define INNERd 1024
#define MLPd   4096
#define Ee     8
#define Bb     4
#define Nn     1024
#define Tt     (Bb*Nn)          // 4096 tokens
#define NEXP   (Ee-1)           // 7 FiLM experts

// ---------------- scratch (device globals; no cudaMalloc allowed) ----------------
__device__ float g_x[Tt*Dm];
__device__ float g_h[Tt*Dm];
__device__ float g_qkv[Tt*3*INNERd];
__device__ float g_scores[(size_t)Bb*Hh*Nn*Nn];
__device__ float g_o[Tt*INNERd];
__device__ float g_t0[Tt*Dm];     // also holds ytf after FiLM elementwise
__device__ float g_t1[Tt*Dm];     // also holds y (mix output)
__device__ float g_pe[(size_t)NEXP*Tt*Dm];
__device__ float g_ae[(size_t)NEXP*Tt*Dm];
__device__ float g_mid[(size_t)Tt*MLPd];
__device__ float g_w[Lnum*Tt*Ee];

__device__ __forceinline__ float gelu_f(float v) {
    return 0.5f * v * (1.0f + erff(v * 0.7071067811865475f));
}

// ---------------- generic tiled SGEMM ----------------
// C[M,N] = A[M,K] @ B[K,N] (+bias[N]) (act) (+resid, same layout as C)
// batched via blockIdx.z: bb=z/Hd, hh=z%Hd, pointer offsets by strides.
// BM=128, BN=64, BK=16; 16x16 threads, 8x4 micro-tile. M%128==0, N%64==0, K%16==0.
__global__ __launch_bounds__(256) void sgemm_kernel(
    const float* __restrict__ A, const float* __restrict__ B,
    const float* __restrict__ bias, const float* __restrict__ resid,
    float* __restrict__ C,
    int M, int N, int K, int lda, int ldb, int ldc,
    int Hd, long sAb, long sAh, long sBb, long sBh, long sCb, long sCh,
    int act, int hasBias, int hasRes)
{
    int z = blockIdx.z;
    int zb = z / Hd, zh = z % Hd;
    A += zb * sAb + zh * sAh;
    B += zb * sBb + zh * sBh;
    C += zb * sCb + zh * sCh;
    if (hasRes) resid += zb * sCb + zh * sCh;

    int row0 = blockIdx.y * 128;
    int col0 = blockIdx.x * 64;

    __shared__ float As[16][128];
    __shared__ float Bs[16][64];

    float acc[8][4];
#pragma unroll
    for (int i = 0; i < 8; i++)
#pragma unroll
        for (int j = 0; j < 4; j++) acc[i][j] = 0.f;

    int t = threadIdx.y * 16 + threadIdx.x;

    for (int kt = 0; kt < K; kt += 16) {
        // load A tile 128x16 (transposed into As[k][m])
#pragma unroll
        for (int li = 0; li < 2; li++) {
            int idx = li * 1024 + t * 4;
            int r = idx >> 4, c = idx & 15;
            float4 v = *(const float4*)(A + (long)(row0 + r) * lda + kt + c);
            As[c + 0][r] = v.x; As[c + 1][r] = v.y;
            As[c + 2][r] = v.z; As[c + 3][r] = v.w;
        }
        // load B tile 16x64
        {
            int idx = t * 4;
            int r = idx >> 6, c = idx & 63;
            float4 v = *(const float4*)(B + (long)(kt + r) * ldb + col0 + c);
            *(float4*)&Bs[r][c] = v;
        }
        __syncthreads();
#pragma unroll
        for (int kk = 0; kk < 16; kk++) {
            float4 a0 = *(const float4*)&As[kk][threadIdx.y * 8];
            float4 a1 = *(const float4*)&As[kk][threadIdx.y * 8 + 4];
            float4 b0 = *(const float4*)&Bs[kk][threadIdx.x * 4];
            float av[8] = {a0.x, a0.y, a0.z, a0.w, a1.x, a1.y, a1.z, a1.w};
            float bv[4] = {b0.x, b0.y, b0.z, b0.w};
#pragma unroll
            for (int i = 0; i < 8; i++)
#pragma unroll
                for (int j = 0; j < 4; j++) acc[i][j] += av[i] * bv[j];
        }
        __syncthreads();
    }

#pragma unroll
    for (int i = 0; i < 8; i++) {
        int row = row0 + threadIdx.y * 8 + i;
#pragma unroll
        for (int j = 0; j < 4; j++) {
            int col = col0 + threadIdx.x * 4 + j;
            float v = acc[i][j];
            if (hasBias) v += bias[col];
            if (act == 1) v = gelu_f(v);
            if (hasRes) v += resid[(long)row * ldc + col];
            C[(long)row * ldc + col] = v;
        }
    }
}

// ---------------- QK^T attention scores ----------------
// scores[z, q, k] = (1/8) * sum_d Q[q,d] * K[k,d],  z = b*H + h
__global__ __launch_bounds__(256) void qk_kernel(const float* __restrict__ qkv,
                                                 float* __restrict__ scores)
{
    int z = blockIdx.z;
    int b = z / Hh, h = z % Hh;
    const float* Q = qkv + (long)b * Nn * 3 * INNERd + h * DHh;
    const float* Kp = Q + INNERd;
    int q0 = blockIdx.y * 64, k0 = blockIdx.x * 64;

    __shared__ float Qs[64][68];   // [d][row]
    __shared__ float Ks[64][68];   // [d][col]

    int t = threadIdx.y * 16 + threadIdx.x;
#pragma unroll
    for (int li = 0; li < 16; li++) {
        int idx = li * 256 + t;
        int r = idx >> 6, d = idx & 63;
        Qs[d][r] = Q[(long)(q0 + r) * (3 * INNERd) + d];
        Ks[d][r] = Kp[(long)(k0 + r) * (3 * INNERd) + d];
    }
    __syncthreads();

    float acc[4][4];
#pragma unroll
    for (int i = 0; i < 4; i++)
#pragma unroll
        for (int j = 0; j < 4; j++) acc[i][j] = 0.f;

#pragma unroll 8
    for (int d = 0; d < 64; d++) {
        float4 qv = *(const float4*)&Qs[d][threadIdx.y * 4];
        float4 kv = *(const float4*)&Ks[d][threadIdx.x * 4];
        float av[4] = {qv.x, qv.y, qv.z, qv.w};
        float bv[4] = {kv.x, kv.y, kv.z, kv.w};
#pragma unroll
        for (int i = 0; i < 4; i++)
#pragma unroll
            for (int j = 0; j < 4; j++) acc[i][j] += av[i] * bv[j];
    }

    float* out = scores + (long)z * Nn * Nn;
#pragma unroll
    for (int i = 0; i < 4; i++)
#pragma unroll
        for (int j = 0; j < 4; j++)
            out[(long)(q0 + threadIdx.y * 4 + i) * Nn + k0 + threadIdx.x * 4 + j] =
                acc[i][j] * 0.125f;
}

// ---------------- softmax over last dim (row length Nn) ----------------
__global__ __launch_bounds__(256) void softmax_kernel(float* __restrict__ s)
{
    float* p = s + (size_t)blockIdx.x * Nn;
    int tid = threadIdx.x;
    __shared__ float red[256];

    float v[4];
    float m = -3.4e38f;
#pragma unroll
    for (int i = 0; i < 4; i++) { v[i] = p[tid + i * 256]; m = fmaxf(m, v[i]); }
    red[tid] = m; __syncthreads();
    for (int st = 128; st > 0; st >>= 1) {
        if (tid < st) red[tid] = fmaxf(red[tid], red[tid + st]);
        __syncthreads();
    }
    m = red[0]; __syncthreads();

    float sum = 0.f;
#pragma unroll
    for (int i = 0; i < 4; i++) { v[i] = expf(v[i] - m); sum += v[i]; }
    red[tid] = sum; __syncthreads();
    for (int st = 128; st > 0; st >>= 1) {
        if (tid < st) red[tid] += red[tid + st];
        __syncthreads();
    }
    float inv = 1.f / red[0];
#pragma unroll
    for (int i = 0; i < 4; i++) p[tid + i * 256] = v[i] * inv;
}

// ---------------- LayerNorm ----------------
__global__ __launch_bounds__(256) void ln_kernel(const float* __restrict__ x,
                                                 const float* __restrict__ g,
                                                 const float* __restrict__ bta,
                                                 float* __restrict__ out)
{
    int t = blockIdx.x, tid = threadIdx.x;
    const float* xp = x + (long)t * Dm;
    __shared__ float r1[256], r2[256];

    float v[4], s = 0.f, s2 = 0.f;
#pragma unroll
    for (int i = 0; i < 4; i++) { v[i] = xp[tid + i * 256]; s += v[i]; s2 += v[i] * v[i]; }
    r1[tid] = s; r2[tid] = s2; __syncthreads();
    for (int st = 128; st > 0; st >>= 1) {
        if (tid < st) { r1[tid] += r1[tid + st]; r2[tid] += r2[tid + st]; }
        __syncthreads();
    }
    float mean = r1[0] * (1.f / Dm);
    float var = r2[0] * (1.f / Dm) - mean * mean;
    float rstd = rsqrtf(var + 1e-5f);
    float* op = out + (long)t * Dm;
#pragma unroll
    for (int i = 0; i < 4; i++) {
        int d = tid + i * 256;
        op[d] = (v[i] - mean) * rstd * g[d] + bta[d];
    }
}

// ---------------- router: logits -> keep top-2 -> softmax ----------------
__global__ __launch_bounds__(128) void router_kernel(const float* __restrict__ x,
                                                     const float* __restrict__ Wr,
                                                     const float* __restrict__ br,
                                                     float* __restrict__ wout)
{
    int t = blockIdx.x, tid = threadIdx.x;
    __shared__ float part[128][Ee];
    float acc[Ee];
#pragma unroll
    for (int e = 0; e < Ee; e++) acc[e] = 0.f;
    const float* xp = x + (long)t * Dm;
    for (int d = tid; d < Dm; d += 128) {
        float xv = xp[d];
        const float* wrow = Wr + (long)d * Ee;
#pragma unroll
        for (int e = 0; e < Ee; e++) acc[e] += xv * wrow[e];
    }
#pragma unroll
    for (int e = 0; e < Ee; e++) part[tid][e] = acc[e];
    __syncthreads();
    for (int st = 64; st > 0; st >>= 1) {
        if (tid < st)
#pragma unroll
            for (int e = 0; e < Ee; e++) part[tid][e] += part[tid + st][e];
        __syncthreads();
    }
    if (tid == 0) {
        float lg[Ee];
#pragma unroll
        for (int e = 0; e < Ee; e++) lg[e] = part[0][e] + br[e];
        float m1 = -3.4e38f, m2 = -3.4e38f;
#pragma unroll
        for (int e = 0; e < Ee; e++) {
            float v = lg[e];
            if (v > m1) { m2 = m1; m1 = v; }
            else if (v > m2) m2 = v;
        }
        float sum = 0.f, we[Ee];
#pragma unroll
        for (int e = 0; e < Ee; e++) {
            we[e] = (lg[e] < m2) ? 0.f : expf(lg[e] - m1);
            sum += we[e];
        }
        float inv = 1.f / sum;
#pragma unroll
        for (int e = 0; e < Ee; e++) wout[(long)t * Ee + e] = we[e] * inv;
    }
}

// ---------------- FiLM elementwise: t0 = gelu(t0) * t1 ----------------
__global__ __launch_bounds__(256) void film_kernel(float* __restrict__ t0,
                                                   const float* __restrict__ t1)
{
    long i = (long)blockIdx.x * 256 + threadIdx.x;
    t0[i] = gelu_f(t0[i]) * t1[i];
}

// ---------------- expert mixing ----------------
// y = w0*gelu(ytf) + sum_{e=1..7} w_e * ((pe_e + Pb_e)*ytf + ae_e + Ab_e)
__global__ __launch_bounds__(256) void mix_kernel(const float* __restrict__ ytf,
                                                  const float* __restrict__ pe,
                                                  const float* __restrict__ ae,
                                                  const float* __restrict__ Pb,
                                                  const float* __restrict__ Ab,
                                                  const float* __restrict__ w,
                                                  float* __restrict__ y)
{
    int t = blockIdx.x;
    __shared__ float ws[Ee];
    if (threadIdx.x < Ee) ws[threadIdx.x] = w[(long)t * Ee + threadIdx.x];
    __syncthreads();
#pragma unroll
    for (int it = 0; it < 4; it++) {
        int d = threadIdx.x + it * 256;
        long td = (long)t * Dm + d;
        float yv = ytf[td];
        float out = ws[0] * gelu_f(yv);
#pragma unroll
        for (int e = 0; e < NEXP; e++) {
            float we = ws[e + 1];
            if (we != 0.f) {
                float p = pe[(long)e * Tt * Dm + td] + Pb[e * Dm + d];
                float a = ae[(long)e * Tt * Dm + td] + Ab[e * Dm + d];
                out += we * (p * yv + a);
            }
        }
        y[td] = out;
    }
}

// ---------------- host-side helpers ----------------
static float* sym(const void* s) {
    void* p = nullptr;
    cudaGetSymbolAddress(&p, s);
    return (float*)p;
}

static void gemm(const float* A, const float* B, const float* bias, const float* resid,
                 float* C, int M, int N, int K, int lda, int ldb, int ldc,
                 int Z, int Hd, long sAb, long sAh, long sBb, long sBh, long sCb, long sCh,
                 int act)
{
    dim3 grid(N / 64, M / 128, Z), block(16, 16);
    sgemm_kernel<<<grid, block>>>(A, B, bias, resid, C, M, N, K, lda, ldb, ldc,
                                  Hd, sAb, sAh, sBb, sBh, sCb, sCh,
                                  act, bias != nullptr, resid != nullptr);
}

extern "C" void kernel_launch(void* const* d_in, const int* in_sizes, int n_in,
                              void* d_out, int out_size)
{
    const float* x_in  = (const float*)d_in[0];
    const float* ln1_g = (const float*)d_in[1];
    const float* ln1_b = (const float*)d_in[2];
    const float* Wqkv  = (const float*)d_in[3];
    const float* bqkv  = (const float*)d_in[4];
    const float* Wo    = (const float*)d_in[5];
    const float* bo    = (const float*)d_in[6];
    const float* Wr    = (const float*)d_in[7];
    const float* br    = (const float*)d_in[8];
    const float* Wa1   = (const float*)d_in[9];
    const float* ba1   = (const float*)d_in[10];
    const float* Wa2   = (const float*)d_in[11];
    const float* ba2   = (const float*)d_in[12];
    const float* ln2_g = (const float*)d_in[13];
    const float* ln2_b = (const float*)d_in[14];
    const float* Wb0   = (const float*)d_in[15];
    const float* bb0   = (const float*)d_in[16];
    const float* Wb1   = (const float*)d_in[17];
    const float* bb1   = (const float*)d_in[18];
    const float* We_p  = (const float*)d_in[19];
    const float* be_p  = (const float*)d_in[20];
    const float* We_a  = (const float*)d_in[21];
    const float* be_a  = (const float*)d_in[22];

    float* X   = sym(g_x);
    float* Hb  = sym(g_h);
    float* QKV = sym(g_qkv);
    float* S   = sym(g_scores);
    float* O   = sym(g_o);
    float* T0  = sym(g_t0);
    float* T1  = sym(g_t1);
    float* PE  = sym(g_pe);
    float* AE  = sym(g_ae);
    float* MID = sym(g_mid);
    float* Wt  = sym(g_w);

    cudaMemcpyAsync(X, x_in, (size_t)Tt * Dm * sizeof(float),
                    cudaMemcpyDeviceToDevice, 0);

    for (int l = 0; l < Lnum; l++) {
        // --- attention block ---
        ln_kernel<<<Tt, 256>>>(X, ln1_g + l * Dm, ln1_b + l * Dm, Hb);

        gemm(Hb, Wqkv + (long)l * Dm * 3 * INNERd, bqkv + (long)l * 3 * INNERd, nullptr,
             QKV, Tt, 3 * INNERd, Dm, Dm, 3 * INNERd, 3 * INNERd,
             1, 1, 0, 0, 0, 0, 0, 0, 0);

        {
            dim3 grid(Nn / 64, Nn / 64, Bb * Hh), block(16, 16);
            qk_kernel<<<grid, block>>>(QKV, S);
        }
        softmax_kernel<<<Bb * Hh * Nn, 256>>>(S);

        // O[b,n,h*DH+d] = sum_k S[b,h,n,k] * V[b,k,h*DH+d]
        gemm(S, QKV + 2 * INNERd, nullptr, nullptr, O,
             Nn, DHh, Nn, Nn, 3 * INNERd, INNERd,
             Bb * Hh, Hh,
             (long)Hh * Nn * Nn, (long)Nn * Nn,
             (long)Nn * 3 * INNERd, DHh,
             (long)Nn * INNERd, DHh, 0);

        // x = O @ Wo + bo + x
        gemm(O, Wo + (long)l * INNERd * Dm, bo + (long)l * Dm, X, X,
             Tt, Dm, INNERd, INNERd, Dm, Dm,
             1, 1, 0, 0, 0, 0, 0, 0, 0);

        // --- router ---
        router_kernel<<<Tt, 128>>>(X, Wr + (long)l * Dm * Ee, br + (long)l * Ee,
                                   Wt + (long)l * Tt * Ee);

        // --- FiLM trunk ---
        ln_kernel<<<Tt, 256>>>(X, ln2_g + l * Dm, ln2_b + l * Dm, Hb);
        gemm(Hb, Wb0 + (long)l * Dm * Dm, bb0 + (long)l * Dm, nullptr, T0,
             Tt, Dm, Dm, Dm, Dm, Dm, 1, 1, 0, 0, 0, 0, 0, 0, 0);
        gemm(Hb, Wb1 + (long)l * Dm * Dm, bb1 + (long)l * Dm, nullptr, T1,
             Tt, Dm, Dm, Dm, Dm, Dm, 1, 1, 0, 0, 0, 0, 0, 0, 0);
        film_kernel<<<(Tt * Dm) / 256, 256>>>(T0, T1);   // T0 := ytf

        // --- dense expert GEMMs (batched over 7 experts) ---
        gemm(T0, We_p + (long)l * NEXP * Dm * Dm, nullptr, nullptr, PE,
             Tt, Dm, Dm, Dm, Dm, Dm,
             NEXP, 1, 0, 0, (long)Dm * Dm, 0, (long)Tt * Dm, 0, 0);
        gemm(T0, We_a + (long)l * NEXP * Dm * Dm, nullptr, nullptr, AE,
             Tt, Dm, Dm, Dm, Dm, Dm,
             NEXP, 1, 0, 0, (long)Dm * Dm, 0, (long)Tt * Dm, 0, 0);

        // --- mix (T1 := y) ---
        mix_kernel<<<Tt, 256>>>(T0, PE, AE,
                                be_p + (long)l * NEXP * Dm,
                                be_a + (long)l * NEXP * Dm,
                                Wt + (long)l * Tt * Ee, T1);

        // --- adaptor MLP + residual ---
        gemm(T1, Wa1 + (long)l * Dm * MLPd, ba1 + (long)l * MLPd, nullptr, MID,
             Tt, MLPd, Dm, Dm, MLPd, MLPd, 1, 1, 0, 0, 0, 0, 0, 0, 1 /*gelu*/);
        gemm(MID, Wa2 + (long)l * MLPd * Dm, ba2 + (long)l * Dm, X, X,
             Tt, Dm, MLPd, MLPd, Dm, Dm, 1, 1, 0, 0, 0, 0, 0, 0, 0);
    }

    // outputs: x [B,N,D] then stacked router weights [L,B,N,E]
    cudaMemcpyAsync(d_out, X, (size_t)Tt * Dm * sizeof(float),
                    cudaMemcpyDeviceToDevice, 0);
    if (out_size >= Tt * Dm + Lnum * Tt * Ee) {
        cudaMemcpyAsync((float*)d_out + (size_t)Tt * Dm, Wt,
                        (size_t)Lnum * Tt * Ee * sizeof(float),
                        cudaMemcpyDeviceToDevice, 0);
    }
}